// round 11
// baseline (speedup 1.0000x reference)
#include <cuda_runtime.h>
#include <cuda_fp16.h>
#include <cstdint>

#define D_MODEL 1024
#define NHEAD   16
#define DHEAD   64
#define SEQ     2048
#define MAXB    2
#define NACT    (MAXB * SEQ * D_MODEL)
#define NW      (D_MODEL * D_MODEL)

// Scratch planes (no device allocation allowed)
__device__ __half g_ah[3][NACT], g_al[3][NACT];   // split activations q,k,v
__device__ __half g_wh[4][NW];                    // split weights (hi) q,k,v,o
__device__ __half g_qh[NACT], g_ql[NACT];
__device__ __half g_kh[NACT], g_vh[NACT];
__device__ __half g_ctxh[NACT], g_ctxl[NACT];

// ===========================================================================
// Helpers
// ===========================================================================
__device__ __forceinline__ uint32_t smem_u32(const void* p) {
    uint32_t a;
    asm("{ .reg .u64 t; cvta.to.shared.u64 t, %1; cvt.u32.u64 %0, t; }"
        : "=r"(a) : "l"(p));
    return a;
}

__device__ __forceinline__ void ldsm4(uint32_t* r, uint32_t addr) {
    asm volatile("ldmatrix.sync.aligned.m8n8.x4.shared.b16 {%0,%1,%2,%3}, [%4];"
        : "=r"(r[0]), "=r"(r[1]), "=r"(r[2]), "=r"(r[3]) : "r"(addr));
}

__device__ __forceinline__ void ldsm4t(uint32_t* r, uint32_t addr) {
    asm volatile("ldmatrix.sync.aligned.m8n8.x4.trans.shared.b16 {%0,%1,%2,%3}, [%4];"
        : "=r"(r[0]), "=r"(r[1]), "=r"(r[2]), "=r"(r[3]) : "r"(addr));
}

__device__ __forceinline__ void mma_f16(float* d, const uint32_t* a, const uint32_t* b) {
    asm volatile(
        "mma.sync.aligned.m16n8k16.row.col.f32.f16.f16.f32 "
        "{%0,%1,%2,%3}, {%4,%5,%6,%7}, {%8,%9}, {%0,%1,%2,%3};"
        : "+f"(d[0]), "+f"(d[1]), "+f"(d[2]), "+f"(d[3])
        : "r"(a[0]), "r"(a[1]), "r"(a[2]), "r"(a[3]), "r"(b[0]), "r"(b[1]));
}

__device__ __forceinline__ uint32_t pack_h(float e, float o) {
    __half2 t = __floats2half2_rn(e, o);
    return *reinterpret_cast<uint32_t*>(&t);
}

__device__ __forceinline__ void split2h(float a, float b, uint32_t& hi, uint32_t& lo) {
    __half2 h = __floats2half2_rn(a, b);
    hi = *reinterpret_cast<uint32_t*>(&h);
    float la = a - __half2float(__low2half(h));
    float lb = b - __half2float(__high2half(h));
    lo = pack_h(la, lb);
}

__device__ __forceinline__ void cpa16(uint32_t dst, const void* src) {
    asm volatile("cp.async.cg.shared.global [%0], [%1], 16;"
                 :: "r"(dst), "l"(src) : "memory");
}
#define CP_COMMIT() asm volatile("cp.async.commit_group;" ::: "memory")
#define CP_WAIT(n)  asm volatile("cp.async.wait_group %0;" :: "n"(n) : "memory")

// ===========================================================================
// One-time split kernels (bandwidth-bound)
// ===========================================================================
__global__ void split_act_kernel(const float* __restrict__ q,
                                 const float* __restrict__ k,
                                 const float* __restrict__ v, int n4)
{
    const int z = blockIdx.z;
    const float4* src = (const float4*)((z == 0) ? q : (z == 1) ? k : v);
    uint2* dh = (uint2*)g_ah[z];
    uint2* dl = (uint2*)g_al[z];
    for (int i = blockIdx.x * blockDim.x + threadIdx.x; i < n4;
         i += gridDim.x * blockDim.x) {
        float4 a = src[i];
        uint32_t h01, l01, h23, l23;
        split2h(a.x, a.y, h01, l01);
        split2h(a.z, a.w, h23, l23);
        dh[i] = make_uint2(h01, h23);
        dl[i] = make_uint2(l01, l23);
    }
}

__global__ void split_w_kernel(const float* __restrict__ w0, const float* __restrict__ w1,
                               const float* __restrict__ w2, const float* __restrict__ w3)
{
    const int z = blockIdx.z;
    const float4* src = (const float4*)((z == 0) ? w0 : (z == 1) ? w1 : (z == 2) ? w2 : w3);
    uint2* dh = (uint2*)g_wh[z];
    const int n4 = NW / 4;
    for (int i = blockIdx.x * blockDim.x + threadIdx.x; i < n4;
         i += gridDim.x * blockDim.x) {
        float4 a = src[i];
        dh[i] = make_uint2(pack_h(a.x, a.y), pack_h(a.z, a.w));
    }
}

// ===========================================================================
// GEMM body (pre-split planes): Y = A @ B^T + bias
// fp32 via fp16 2-term: acc = Ah@Bh + Al@Bh.
// CTA 128x128, 8 warps, BK=32, 2-stage cp.async double buffer.
// Compute-side smem addressing identical to R10.
// ===========================================================================
#define GBK 32
#define GNCHUNK (D_MODEL / GBK)

template <bool SPLIT>
__device__ __forceinline__ void gemm_body(
    const __half* __restrict__ Ah, const __half* __restrict__ Al,
    const __half* __restrict__ Bh,
    const float* __restrict__ bias, float* __restrict__ Y,
    __half* __restrict__ Yh, __half* __restrict__ Yl)
{
    __shared__ __align__(1024) uint8_t sS[2][32768];   // per stage: A 16K | B 16K (even slots)
    const uint32_t sbase = smem_u32(sS);

    const int tid  = threadIdx.x;
    const int wid  = tid >> 5;
    const int lane = tid & 31;
    const int m0 = blockIdx.y * 128;
    const int n0 = blockIdx.x * 128;
    const int wm = (wid >> 2) * 64;
    const int wn = (wid & 3) * 32;

    // staging: chunk id e in [0,512): row = e>>2, gk = e&3 (16B chunk within 64B row)
    const int s_row = tid >> 2;        // +64 per i-iter
    const int s_gk  = tid & 3;

#define STAGE_CHUNK(c_)                                                            \
    {                                                                              \
        const int k0_ = (c_) * GBK;                                                \
        const uint32_t dA_ = sbase + (uint32_t)((c_) & 1) * 32768;                 \
        const uint32_t dB_ = dA_ + 16384;                                          \
        _Pragma("unroll")                                                          \
        for (int i_ = 0; i_ < 2; i_++) {                                           \
            int row_ = s_row + i_ * 64;                                            \
            int r7_ = row_ & 7;                                                    \
            uint32_t offH_ = (uint32_t)(row_ * 128 + (((2 * s_gk)     ^ r7_) << 4)); \
            uint32_t offL_ = (uint32_t)(row_ * 128 + (((2 * s_gk + 1) ^ r7_) << 4)); \
            const size_t sa_ = (size_t)(m0 + row_) * D_MODEL + k0_ + s_gk * 8;     \
            cpa16(dA_ + offH_, Ah + sa_);                                          \
            cpa16(dA_ + offL_, Al + sa_);                                          \
            const size_t sb_ = (size_t)(n0 + row_) * D_MODEL + k0_ + s_gk * 8;     \
            cpa16(dB_ + offH_, Bh + sb_);                                          \
        }                                                                          \
        CP_COMMIT();                                                               \
    }

    float acc[4][4][4];
#pragma unroll
    for (int i = 0; i < 4; i++)
#pragma unroll
        for (int g = 0; g < 4; g++)
#pragma unroll
            for (int r = 0; r < 4; r++) acc[i][g][r] = 0.f;

    STAGE_CHUNK(0);
    STAGE_CHUNK(1);

    for (int c = 0; c < GNCHUNK; c++) {
        if (c + 1 < GNCHUNK) { CP_WAIT(1); } else { CP_WAIT(0); }
        __syncthreads();

        const uint32_t sA = sbase + (uint32_t)(c & 1) * 32768;
        const uint32_t sB = sA + 16384;

#pragma unroll
        for (int ks = 0; ks < 2; ks++) {
            uint32_t aH[4][4], aL[4][4], bH[4][2];
            {
                int rA = wm + (lane & 15);
                int cHi = 4 * ks + 2 * ((lane >> 4) & 1);
                int r7 = rA & 7;
                uint32_t base = sA + (uint32_t)rA * 128;
                uint32_t pH = (uint32_t)((cHi ^ r7) << 4);
                uint32_t pL = (uint32_t)(((cHi + 1) ^ r7) << 4);
#pragma unroll
                for (int i = 0; i < 4; i++) {
                    ldsm4(aH[i], base + i * 2048 + pH);
                    ldsm4(aL[i], base + i * 2048 + pL);
                }
            }
            {
                int rBb = wn + (lane & 7) + ((lane >> 4) & 1) * 8;
                int cHi = 4 * ks + 2 * ((lane >> 3) & 1);
#pragma unroll
                for (int j = 0; j < 2; j++) {
                    int rB = rBb + j * 16;
                    int r7 = rB & 7;
                    uint32_t t[4];
                    ldsm4(t, sB + (uint32_t)rB * 128 + (uint32_t)((cHi ^ r7) << 4));
                    bH[2 * j][0] = t[0]; bH[2 * j][1] = t[1];
                    bH[2 * j + 1][0] = t[2]; bH[2 * j + 1][1] = t[3];
                }
            }
#pragma unroll
            for (int i = 0; i < 4; i++)
#pragma unroll
                for (int g = 0; g < 4; g++) {
                    mma_f16(acc[i][g], aH[i], bH[g]);
                    mma_f16(acc[i][g], aL[i], bH[g]);
                }
        }

        __syncthreads();
        if (c + 2 < GNCHUNK) STAGE_CHUNK(c + 2);
    }
#undef STAGE_CHUNK

    // ---- epilogue ----
#pragma unroll
    for (int i = 0; i < 4; i++) {
        int row = m0 + wm + i * 16 + (lane >> 2);
#pragma unroll
        for (int g = 0; g < 4; g++) {
            int col = n0 + wn + g * 8 + (lane & 3) * 2;
            float2 b2 = *(const float2*)(bias + col);
            float v00 = acc[i][g][0] + b2.x, v01 = acc[i][g][1] + b2.y;
            float v10 = acc[i][g][2] + b2.x, v11 = acc[i][g][3] + b2.y;
            if (SPLIT) {
                uint32_t h, l;
                split2h(v00, v01, h, l);
                *(uint32_t*)(Yh + (size_t)row * D_MODEL + col) = h;
                if (Yl) *(uint32_t*)(Yl + (size_t)row * D_MODEL + col) = l;
                split2h(v10, v11, h, l);
                *(uint32_t*)(Yh + (size_t)(row + 8) * D_MODEL + col) = h;
                if (Yl) *(uint32_t*)(Yl + (size_t)(row + 8) * D_MODEL + col) = l;
            } else {
                float2 o0, o1;
                o0.x = v00; o0.y = v01;
                o1.x = v10; o1.y = v11;
                *(float2*)(Y + (size_t)row * D_MODEL + col) = o0;
                *(float2*)(Y + (size_t)(row + 8) * D_MODEL + col) = o1;
            }
        }
    }
}

// Fused Q/K/V projections: grid.z selects which.
__global__ __launch_bounds__(256, 2) void gemm_qkv_kernel(
    const float* __restrict__ b0, const float* __restrict__ b1, const float* __restrict__ b2)
{
    const int z = blockIdx.z;
    const float* bias = (z == 0) ? b0 : (z == 1) ? b1 : b2;
    __half* Yh = (z == 0) ? g_qh : (z == 1) ? g_kh : g_vh;
    __half* Yl = (z == 0) ? g_ql : nullptr;
    gemm_body<true>(g_ah[z], g_al[z], g_wh[z], bias, nullptr, Yh, Yl);
}

__global__ __launch_bounds__(256, 2) void gemm_out_kernel(
    const float* __restrict__ bias, float* __restrict__ Y)
{
    gemm_body<false>(g_ctxh, g_ctxl, g_wh[3], bias, Y, nullptr, nullptr);
}

// ===========================================================================
// Flash attention (causal), fp16 2-term, cp.async double-buffered (R10).
// Epilogue writes ctx hi/lo planes.
// SMEM: Qh 16K | Ql 16K | buf0 {Kh 8K, Vh 8K} | buf1 = 64K
// ===========================================================================
#define AQ 128
#define AK 64
#define ATTN_SMEM 65536

__global__ __launch_bounds__(256, 2) void attn_mma_kernel()
{
    extern __shared__ uint8_t dsm[];
    const uint32_t sQh = smem_u32(dsm);
    const uint32_t sQl = sQh + 16384;
    const uint32_t sBUF = sQh + 32768;

    const int tid  = threadIdx.x;
    const int wid  = tid >> 5;
    const int lane = tid & 31;
    const int qt = (SEQ / AQ - 1) - blockIdx.x;
    const int h  = blockIdx.y;
    const int b  = blockIdx.z;
    const size_t gbase = ((size_t)b * SEQ) * D_MODEL + (size_t)h * DHEAD;

    const int nkt = 2 * qt + 2;

#pragma unroll
    for (int i = 0; i < 8; i++) {
        const int pl = i >> 2;
        int c = (i & 3) * 256 + tid;
        int row = c >> 3, c16 = c & 7;
        uint32_t dst = (pl ? sQl : sQh) + (uint32_t)(row * 128 + ((c16 ^ (row & 7)) << 4));
        const __half* src = (pl ? g_ql : g_qh) + gbase + (size_t)(qt * AQ + row) * D_MODEL + c16 * 8;
        cpa16(dst, src);
    }
    const __half* kvsrc[2] = { g_kh, g_vh };
#pragma unroll
    for (int i = 0; i < 4; i++) {
        const int pl = i >> 1;
        int c = (i & 1) * 256 + tid;
        int row = c >> 3, c16 = c & 7;
        uint32_t dst = sBUF + pl * 8192 + (uint32_t)(row * 128 + ((c16 ^ (row & 7)) << 4));
        cpa16(dst, kvsrc[pl] + gbase + (size_t)row * D_MODEL + c16 * 8);
    }
    CP_COMMIT();
#pragma unroll
    for (int i = 0; i < 4; i++) {
        const int pl = i >> 1;
        int c = (i & 1) * 256 + tid;
        int row = c >> 3, c16 = c & 7;
        uint32_t dst = sBUF + 16384 + pl * 8192 + (uint32_t)(row * 128 + ((c16 ^ (row & 7)) << 4));
        cpa16(dst, kvsrc[pl] + gbase + (size_t)(AK + row) * D_MODEL + c16 * 8);
    }
    CP_COMMIT();

    uint32_t qfh[4][4], qfl[4][4];
    float O[8][4];
#pragma unroll
    for (int g = 0; g < 8; g++)
#pragma unroll
        for (int r = 0; r < 4; r++) O[g][r] = 0.f;
    float m0 = -1e30f, m1 = -1e30f, l0 = 0.f, l1 = 0.f;

    const int wrow0 = qt * AQ + wid * 16;
    const float scale = 0.125f;

    for (int jt = 0; jt < nkt; jt++) {
        if (jt + 1 < nkt) { CP_WAIT(1); } else { CP_WAIT(0); }
        __syncthreads();

        if (jt == 0) {
#pragma unroll
            for (int ks = 0; ks < 4; ks++) {
                int row = (wid << 4) + (lane & 15);
                int c16 = 2 * ks + (lane >> 4);
                uint32_t addr = (uint32_t)(row * 128 + ((c16 ^ (row & 7)) << 4));
                ldsm4(qfh[ks], sQh + addr);
                ldsm4(qfl[ks], sQl + addr);
            }
        }

        const uint32_t kb = sBUF + (uint32_t)(jt & 1) * 16384;
        const uint32_t sKh = kb, sVh = kb + 8192;

        if (wrow0 + 15 >= jt * AK) {
            float S[8][4];
#pragma unroll
            for (int g = 0; g < 8; g++)
#pragma unroll
                for (int r = 0; r < 4; r++) S[g][r] = 0.f;

#pragma unroll
            for (int ks = 0; ks < 4; ks++) {
                uint32_t kh[4][4];
#pragma unroll
                for (int g2 = 0; g2 < 4; g2++) {
                    int key = g2 * 16 + (lane & 7) + ((lane >> 4) & 1) * 8;
                    int c16 = 2 * ks + ((lane >> 3) & 1);
                    uint32_t addr = (uint32_t)(key * 128 + ((c16 ^ (key & 7)) << 4));
                    ldsm4(kh[g2], sKh + addr);
                }
#pragma unroll
                for (int g2 = 0; g2 < 4; g2++) {
                    mma_f16(S[2 * g2],     qfh[ks], &kh[g2][0]);
                    mma_f16(S[2 * g2],     qfl[ks], &kh[g2][0]);
                    mma_f16(S[2 * g2 + 1], qfh[ks], &kh[g2][2]);
                    mma_f16(S[2 * g2 + 1], qfl[ks], &kh[g2][2]);
                }
            }

            const int r0g = wrow0 + (lane >> 2);
            const bool domask = (jt * AK + 63) > wrow0;
            if (domask) {
                const int key0 = jt * AK + 2 * (lane & 3);
#pragma unroll
                for (int g = 0; g < 8; g++) {
                    int kk = key0 + 8 * g;
                    S[g][0] = (kk     <= r0g)     ? S[g][0] * scale : -1e30f;
                    S[g][1] = (kk + 1 <= r0g)     ? S[g][1] * scale : -1e30f;
                    S[g][2] = (kk     <= r0g + 8) ? S[g][2] * scale : -1e30f;
                    S[g][3] = (kk + 1 <= r0g + 8) ? S[g][3] * scale : -1e30f;
                }
            } else {
#pragma unroll
                for (int g = 0; g < 8; g++) {
                    S[g][0] *= scale; S[g][1] *= scale;
                    S[g][2] *= scale; S[g][3] *= scale;
                }
            }

            float mx0 = S[0][0], mx1 = S[0][2];
#pragma unroll
            for (int g = 0; g < 8; g++) {
                mx0 = fmaxf(mx0, fmaxf(S[g][0], S[g][1]));
                mx1 = fmaxf(mx1, fmaxf(S[g][2], S[g][3]));
            }
            mx0 = fmaxf(mx0, __shfl_xor_sync(0xffffffffu, mx0, 1));
            mx0 = fmaxf(mx0, __shfl_xor_sync(0xffffffffu, mx0, 2));
            mx1 = fmaxf(mx1, __shfl_xor_sync(0xffffffffu, mx1, 1));
            mx1 = fmaxf(mx1, __shfl_xor_sync(0xffffffffu, mx1, 2));
            float mn0 = fmaxf(m0, mx0), mn1 = fmaxf(m1, mx1);
            float corr0 = __expf(m0 - mn0), corr1 = __expf(m1 - mn1);
            m0 = mn0; m1 = mn1;

            float la0 = 0.f, la1 = 0.f;
            uint32_t ph[4][4], pl[4][4];
#pragma unroll
            for (int j = 0; j < 4; j++) {
                float p00 = __expf(S[2 * j][0] - mn0);
                float p01 = __expf(S[2 * j][1] - mn0);
                float p10 = __expf(S[2 * j][2] - mn1);
                float p11 = __expf(S[2 * j][3] - mn1);
                float p20 = __expf(S[2 * j + 1][0] - mn0);
                float p21 = __expf(S[2 * j + 1][1] - mn0);
                float p30 = __expf(S[2 * j + 1][2] - mn1);
                float p31 = __expf(S[2 * j + 1][3] - mn1);
                la0 += p00 + p01 + p20 + p21;
                la1 += p10 + p11 + p30 + p31;
                split2h(p00, p01, ph[j][0], pl[j][0]);
                split2h(p10, p11, ph[j][1], pl[j][1]);
                split2h(p20, p21, ph[j][2], pl[j][2]);
                split2h(p30, p31, ph[j][3], pl[j][3]);
            }
            l0 = l0 * corr0 + la0;
            l1 = l1 * corr1 + la1;
#pragma unroll
            for (int g = 0; g < 8; g++) {
                O[g][0] *= corr0; O[g][1] *= corr0;
                O[g][2] *= corr1; O[g][3] *= corr1;
            }

#pragma unroll
            for (int ks = 0; ks < 4; ks++) {
                uint32_t vh[4][4];
#pragma unroll
                for (int d2 = 0; d2 < 4; d2++) {
                    int row = 16 * ks + (lane & 7) + ((lane >> 3) & 1) * 8;
                    int c16 = 2 * d2 + ((lane >> 4) & 1);
                    uint32_t addr = (uint32_t)(row * 128 + ((c16 ^ (row & 7)) << 4));
                    ldsm4t(vh[d2], sVh + addr);
                }
#pragma unroll
                for (int d2 = 0; d2 < 4; d2++) {
                    mma_f16(O[2 * d2],     ph[ks], &vh[d2][0]);
                    mma_f16(O[2 * d2],     pl[ks], &vh[d2][0]);
                    mma_f16(O[2 * d2 + 1], ph[ks], &vh[d2][2]);
                    mma_f16(O[2 * d2 + 1], pl[ks], &vh[d2][2]);
                }
            }
        }

        __syncthreads();
        if (jt + 2 < nkt) {
#pragma unroll
            for (int i = 0; i < 4; i++) {
                const int pl2 = i >> 1;
                int c = (i & 1) * 256 + tid;
                int row = c >> 3, c16 = c & 7;
                uint32_t dst = sBUF + (uint32_t)(jt & 1) * 16384 + pl2 * 8192
                             + (uint32_t)(row * 128 + ((c16 ^ (row & 7)) << 4));
                cpa16(dst, kvsrc[pl2] + gbase + (size_t)((jt + 2) * AK + row) * D_MODEL + c16 * 8);
            }
            CP_COMMIT();
        }
    }

    // ---- epilogue: normalize, split, write ctx planes ----
    l0 += __shfl_xor_sync(0xffffffffu, l0, 1);
    l0 += __shfl_xor_sync(0xffffffffu, l0, 2);
    l1 += __shfl_xor_sync(0xffffffffu, l1, 1);
    l1 += __shfl_xor_sync(0xffffffffu, l1, 2);
    float inv0 = 1.f / l0, inv1 = 1.f / l1;
    const int r0g = wrow0 + (lane >> 2);
#pragma unroll
    for (int g = 0; g < 8; g++) {
        int dim = 8 * g + 2 * (lane & 3);
        uint32_t hh, ll;
        split2h(O[g][0] * inv0, O[g][1] * inv0, hh, ll);
        *(uint32_t*)(g_ctxh + gbase + (size_t)r0g * D_MODEL + dim) = hh;
        *(uint32_t*)(g_ctxl + gbase + (size_t)r0g * D_MODEL + dim) = ll;
        split2h(O[g][2] * inv1, O[g][3] * inv1, hh, ll);
        *(uint32_t*)(g_ctxh + gbase + (size_t)(r0g + 8) * D_MODEL + dim) = hh;
        *(uint32_t*)(g_ctxl + gbase + (size_t)(r0g + 8) * D_MODEL + dim) = ll;
    }
}

// ===========================================================================
extern "C" void kernel_launch(void* const* d_in, const int* in_sizes, int n_in,
                              void* d_out, int out_size)
{
    const float* query = (const float*)d_in[0];
    const float* key   = (const float*)d_in[1];
    const float* value = (const float*)d_in[2];
    // d_in[3] = mask — causal, applied analytically in-kernel
    const float* w_q = (const float*)d_in[4];
    const float* b_q = (const float*)d_in[5];
    const float* w_k = (const float*)d_in[6];
    const float* b_k = (const float*)d_in[7];
    const float* w_v = (const float*)d_in[8];
    const float* b_v = (const float*)d_in[9];
    const float* w_o = (const float*)d_in[10];
    const float* b_o = (const float*)d_in[11];
    float* out = (float*)d_out;

    const int M  = in_sizes[0] / D_MODEL;   // B * S
    const int Bn = M / SEQ;

    cudaFuncSetAttribute(attn_mma_kernel,
                         cudaFuncAttributeMaxDynamicSharedMemorySize, ATTN_SMEM);

    split_act_kernel<<<dim3(512, 1, 3), 256>>>(query, key, value, M * D_MODEL / 4);
    split_w_kernel<<<dim3(256, 1, 4), 256>>>(w_q, w_k, w_v, w_o);

    gemm_qkv_kernel<<<dim3(D_MODEL / 128, M / 128, 3), 256>>>(b_q, b_k, b_v);

    attn_mma_kernel<<<dim3(SEQ / AQ, NHEAD, Bn), 256, ATTN_SMEM>>>();

    gemm_out_kernel<<<dim3(D_MODEL / 128, M / 128), 256>>>(b_o, out);
}

// round 13
// speedup vs baseline: 1.3129x; 1.3129x over previous
#include <cuda_runtime.h>
#include <cuda_fp16.h>
#include <cstdint>

#define D_MODEL 1024
#define NHEAD   16
#define DHEAD   64
#define SEQ     2048
#define MAXB    2
#define NACT    (MAXB * SEQ * D_MODEL)
#define NW      (D_MODEL * D_MODEL)

// Scratch (no device allocation allowed)
__device__ __half g_qh[NACT], g_ql[NACT];
__device__ __half g_kh[NACT], g_vh[NACT];
__device__ __half g_ctxh[NACT], g_ctxl[NACT];
__device__ __half g_wh[4][NW];               // pre-split weight hi planes q,k,v,o

// ===========================================================================
// Helpers
// ===========================================================================
__device__ __forceinline__ uint32_t smem_u32(const void* p) {
    uint32_t a;
    asm("{ .reg .u64 t; cvta.to.shared.u64 t, %1; cvt.u32.u64 %0, t; }"
        : "=r"(a) : "l"(p));
    return a;
}

__device__ __forceinline__ void ldsm4(uint32_t* r, uint32_t addr) {
    asm volatile("ldmatrix.sync.aligned.m8n8.x4.shared.b16 {%0,%1,%2,%3}, [%4];"
        : "=r"(r[0]), "=r"(r[1]), "=r"(r[2]), "=r"(r[3]) : "r"(addr));
}

__device__ __forceinline__ void ldsm4t(uint32_t* r, uint32_t addr) {
    asm volatile("ldmatrix.sync.aligned.m8n8.x4.trans.shared.b16 {%0,%1,%2,%3}, [%4];"
        : "=r"(r[0]), "=r"(r[1]), "=r"(r[2]), "=r"(r[3]) : "r"(addr));
}

__device__ __forceinline__ void mma_f16(float* d, const uint32_t* a, const uint32_t* b) {
    asm volatile(
        "mma.sync.aligned.m16n8k16.row.col.f32.f16.f16.f32 "
        "{%0,%1,%2,%3}, {%4,%5,%6,%7}, {%8,%9}, {%0,%1,%2,%3};"
        : "+f"(d[0]), "+f"(d[1]), "+f"(d[2]), "+f"(d[3])
        : "r"(a[0]), "r"(a[1]), "r"(a[2]), "r"(a[3]), "r"(b[0]), "r"(b[1]));
}

__device__ __forceinline__ uint32_t pack_h(float e, float o) {
    __half2 t = __floats2half2_rn(e, o);
    return *reinterpret_cast<uint32_t*>(&t);
}

__device__ __forceinline__ void split2h(float a, float b, uint32_t& hi, uint32_t& lo) {
    __half2 h = __floats2half2_rn(a, b);
    hi = *reinterpret_cast<uint32_t*>(&h);
    float la = a - __half2float(__low2half(h));
    float lb = b - __half2float(__high2half(h));
    lo = pack_h(la, lb);
}

__device__ __forceinline__ void sts_v2(uint32_t addr, uint32_t v0, uint32_t v1) {
    asm volatile("st.shared.v2.b32 [%0], {%1,%2};" :: "r"(addr), "r"(v0), "r"(v1) : "memory");
}

__device__ __forceinline__ void cpa16(uint32_t dst, const void* src) {
    asm volatile("cp.async.cg.shared.global [%0], [%1], 16;"
                 :: "r"(dst), "l"(src) : "memory");
}
#define CP_COMMIT() asm volatile("cp.async.commit_group;" ::: "memory")
#define CP_WAIT(n)  asm volatile("cp.async.wait_group %0;" :: "n"(n) : "memory")

// ===========================================================================
// One-time weight split (hi planes only, bandwidth-bound, ~8MB traffic)
// ===========================================================================
__global__ void split_w_kernel(const float* __restrict__ w0, const float* __restrict__ w1,
                               const float* __restrict__ w2, const float* __restrict__ w3)
{
    const int z = blockIdx.z;
    const float4* src = (const float4*)((z == 0) ? w0 : (z == 1) ? w1 : (z == 2) ? w2 : w3);
    uint2* dh = (uint2*)g_wh[z];
    const int n4 = NW / 4;
    for (int i = blockIdx.x * blockDim.x + threadIdx.x; i < n4;
         i += gridDim.x * blockDim.x) {
        float4 a = src[i];
        dh[i] = make_uint2(pack_h(a.x, a.y), pack_h(a.z, a.w));
    }
}

// ===========================================================================
// GEMM body: Y[M,N] = A @ W^T + bias,  fp32 via fp16 2-term (Ah@Wh + Al@Wh)
// CTA 128x128, 8 warps, BK=32, double-buffered smem (R10 skeleton, LDG+STS).
// W comes pre-split (hi plane).  A either fp32 (in-kernel split) or
// pre-split hi/lo planes (PRESPLIT_A).
// ===========================================================================
#define GBK 32
#define GNCHUNK (D_MODEL / GBK)

template <bool SPLIT_OUT, bool PRESPLIT_A>
__device__ __forceinline__ void gemm_body(
    const float* __restrict__ X,
    const __half* __restrict__ Ah, const __half* __restrict__ Al,
    const __half* __restrict__ Wh,
    const float* __restrict__ bias, float* __restrict__ Y,
    __half* __restrict__ Yh, __half* __restrict__ Yl)
{
    __shared__ __align__(1024) uint8_t sS[2][32768];   // per stage: A 16K | B 16K (even slots)
    const uint32_t sbase = smem_u32(sS);

    const int tid  = threadIdx.x;
    const int wid  = tid >> 5;
    const int lane = tid & 31;
    const int m0 = blockIdx.y * 128;
    const int n0 = blockIdx.x * 128;
    const int wm = (wid >> 2) * 64;
    const int wn = (wid & 3) * 32;

    const int s_row = tid >> 3;
    const int s_c4  = tid & 7;
    const int s_g   = s_c4 >> 1;
    const int s_sub = (s_c4 & 1) * 8;

    float acc[4][4][4];
#pragma unroll
    for (int i = 0; i < 4; i++)
#pragma unroll
        for (int g = 0; g < 4; g++)
#pragma unroll
            for (int r = 0; r < 4; r++) acc[i][g][r] = 0.f;

    // ---- prologue: stage chunk 0 into buf0 (synchronous) ----
    {
        const uint32_t dA = sbase, dB = sbase + 16384;
#pragma unroll
        for (int i = 0; i < 4; i++) {
            int row = s_row + i * 32;
            int r7 = row & 7;
            uint32_t offH = (uint32_t)(row * 128 + (((2 * s_g)     ^ r7) << 4) + s_sub);
            uint32_t offL = (uint32_t)(row * 128 + (((2 * s_g + 1) ^ r7) << 4) + s_sub);
            if (PRESPLIT_A) {
                uint2 h2 = *(const uint2*)(Ah + (size_t)(m0 + row) * D_MODEL + s_c4 * 4);
                uint2 l2 = *(const uint2*)(Al + (size_t)(m0 + row) * D_MODEL + s_c4 * 4);
                sts_v2(dA + offH, h2.x, h2.y);
                sts_v2(dA + offL, l2.x, l2.y);
            } else {
                float4 a = *(const float4*)(X + (size_t)(m0 + row) * D_MODEL + s_c4 * 4);
                uint32_t h01, l01, h23, l23;
                split2h(a.x, a.y, h01, l01);
                split2h(a.z, a.w, h23, l23);
                sts_v2(dA + offH, h01, h23);
                sts_v2(dA + offL, l01, l23);
            }
            uint2 w2 = *(const uint2*)(Wh + (size_t)(n0 + row) * D_MODEL + s_c4 * 4);
            sts_v2(dB + offH, w2.x, w2.y);
        }
    }
    __syncthreads();

    for (int c = 0; c < GNCHUNK; c++) {
        // ---- prefetch A for chunk c+1 (in flight over compute) ----
        float4 ra[4];
        uint2 rah[4], ral[4];
        const bool pf = (c + 1 < GNCHUNK);
        if (pf) {
            const int k0n = (c + 1) * GBK;
#pragma unroll
            for (int i = 0; i < 4; i++) {
                int row = s_row + i * 32;
                if (PRESPLIT_A) {
                    rah[i] = *(const uint2*)(Ah + (size_t)(m0 + row) * D_MODEL + k0n + s_c4 * 4);
                    ral[i] = *(const uint2*)(Al + (size_t)(m0 + row) * D_MODEL + k0n + s_c4 * 4);
                } else {
                    ra[i] = *(const float4*)(X + (size_t)(m0 + row) * D_MODEL + k0n + s_c4 * 4);
                }
            }
        }

        const uint32_t sA = sbase + (uint32_t)(c & 1) * 32768;
        const uint32_t sB = sA + 16384;

        // ---- compute chunk c ----
#pragma unroll
        for (int ks = 0; ks < 2; ks++) {
            uint32_t aH[4][4], aL[4][4], bH[4][2];
            {
                int rA = wm + (lane & 15);
                int cHi = 4 * ks + 2 * ((lane >> 4) & 1);
                int r7 = rA & 7;
                uint32_t base = sA + (uint32_t)rA * 128;
                uint32_t pH = (uint32_t)((cHi ^ r7) << 4);
                uint32_t pL = (uint32_t)(((cHi + 1) ^ r7) << 4);
#pragma unroll
                for (int i = 0; i < 4; i++) {
                    ldsm4(aH[i], base + i * 2048 + pH);
                    ldsm4(aL[i], base + i * 2048 + pL);
                }
            }
            {
                int rBb = wn + (lane & 7) + ((lane >> 4) & 1) * 8;
                int cHi = 4 * ks + 2 * ((lane >> 3) & 1);
#pragma unroll
                for (int j = 0; j < 2; j++) {
                    int rB = rBb + j * 16;
                    int r7 = rB & 7;
                    uint32_t t[4];
                    ldsm4(t, sB + (uint32_t)rB * 128 + (uint32_t)((cHi ^ r7) << 4));
                    bH[2 * j][0] = t[0]; bH[2 * j][1] = t[1];
                    bH[2 * j + 1][0] = t[2]; bH[2 * j + 1][1] = t[3];
                }
            }
#pragma unroll
            for (int i = 0; i < 4; i++)
#pragma unroll
                for (int g = 0; g < 4; g++) {
                    mma_f16(acc[i][g], aH[i], bH[g]);
                    mma_f16(acc[i][g], aL[i], bH[g]);
                }
        }

        // ---- deferred: STS prefetched A; load W hi; STS into buf (c+1)&1 ----
        if (pf) {
            const int k0n = (c + 1) * GBK;
            const uint32_t dA = sbase + (uint32_t)((c + 1) & 1) * 32768;
            const uint32_t dB = dA + 16384;
#pragma unroll
            for (int i = 0; i < 4; i++) {
                int row = s_row + i * 32;
                int r7 = row & 7;
                uint32_t offH = (uint32_t)(row * 128 + (((2 * s_g)     ^ r7) << 4) + s_sub);
                uint32_t offL = (uint32_t)(row * 128 + (((2 * s_g + 1) ^ r7) << 4) + s_sub);
                if (PRESPLIT_A) {
                    sts_v2(dA + offH, rah[i].x, rah[i].y);
                    sts_v2(dA + offL, ral[i].x, ral[i].y);
                } else {
                    uint32_t h01, l01, h23, l23;
                    split2h(ra[i].x, ra[i].y, h01, l01);
                    split2h(ra[i].z, ra[i].w, h23, l23);
                    sts_v2(dA + offH, h01, h23);
                    sts_v2(dA + offL, l01, l23);
                }
                uint2 w2 = *(const uint2*)(Wh + (size_t)(n0 + row) * D_MODEL + k0n + s_c4 * 4);
                sts_v2(dB + offH, w2.x, w2.y);
            }
        }
        __syncthreads();
    }

    // ---- epilogue ----
#pragma unroll
    for (int i = 0; i < 4; i++) {
        int row = m0 + wm + i * 16 + (lane >> 2);
#pragma unroll
        for (int g = 0; g < 4; g++) {
            int col = n0 + wn + g * 8 + (lane & 3) * 2;
            float2 b2 = *(const float2*)(bias + col);
            float v00 = acc[i][g][0] + b2.x, v01 = acc[i][g][1] + b2.y;
            float v10 = acc[i][g][2] + b2.x, v11 = acc[i][g][3] + b2.y;
            if (SPLIT_OUT) {
                uint32_t h, l;
                split2h(v00, v01, h, l);
                *(uint32_t*)(Yh + (size_t)row * D_MODEL + col) = h;
                if (Yl) *(uint32_t*)(Yl + (size_t)row * D_MODEL + col) = l;
                split2h(v10, v11, h, l);
                *(uint32_t*)(Yh + (size_t)(row + 8) * D_MODEL + col) = h;
                if (Yl) *(uint32_t*)(Yl + (size_t)(row + 8) * D_MODEL + col) = l;
            } else {
                float2 o0, o1;
                o0.x = v00; o0.y = v01;
                o1.x = v10; o1.y = v11;
                *(float2*)(Y + (size_t)row * D_MODEL + col) = o0;
                *(float2*)(Y + (size_t)(row + 8) * D_MODEL + col) = o1;
            }
        }
    }
}

// Fused Q/K/V projections: grid.z selects which.
// Q gets hi+lo planes; K,V hi only.  W from pre-split plane.
__global__ __launch_bounds__(256, 2) void gemm_qkv_kernel(
    const float* __restrict__ x0, const float* __restrict__ x1, const float* __restrict__ x2,
    const float* __restrict__ bi0, const float* __restrict__ bi1, const float* __restrict__ bi2)
{
    const int z = blockIdx.z;
    const float* X = (z == 0) ? x0 : (z == 1) ? x1 : x2;
    const float* B = (z == 0) ? bi0 : (z == 1) ? bi1 : bi2;
    __half* Yh = (z == 0) ? g_qh : (z == 1) ? g_kh : g_vh;
    __half* Yl = (z == 0) ? g_ql : nullptr;
    gemm_body<true, false>(X, nullptr, nullptr, g_wh[z], B, nullptr, Yh, Yl);
}

__global__ __launch_bounds__(256, 2) void gemm_out_kernel(
    const float* __restrict__ bias, float* __restrict__ Y)
{
    gemm_body<false, true>(nullptr, g_ctxh, g_ctxl, g_wh[3], bias, Y, nullptr, nullptr);
}

// ===========================================================================
// Flash attention (causal), fp16 2-term, cp.async double-buffered (R10).
// Epilogue writes ctx hi/lo planes (bit-identical to out-GEMM's own split).
// SMEM: Qh 16K | Ql 16K | buf0 {Kh 8K, Vh 8K} | buf1 = 64K
// ===========================================================================
#define AQ 128
#define AK 64
#define ATTN_SMEM 65536

__global__ __launch_bounds__(256, 2) void attn_mma_kernel()
{
    extern __shared__ uint8_t dsm[];
    const uint32_t sQh = smem_u32(dsm);
    const uint32_t sQl = sQh + 16384;
    const uint32_t sBUF = sQh + 32768;

    const int tid  = threadIdx.x;
    const int wid  = tid >> 5;
    const int lane = tid & 31;
    const int qt = (SEQ / AQ - 1) - blockIdx.x;   // biggest tiles first
    const int h  = blockIdx.y;
    const int b  = blockIdx.z;
    const size_t gbase = ((size_t)b * SEQ) * D_MODEL + (size_t)h * DHEAD;

    const int nkt = 2 * qt + 2;

#pragma unroll
    for (int i = 0; i < 8; i++) {
        const int pl = i >> 2;
        int c = (i & 3) * 256 + tid;
        int row = c >> 3, c16 = c & 7;
        uint32_t dst = (pl ? sQl : sQh) + (uint32_t)(row * 128 + ((c16 ^ (row & 7)) << 4));
        const __half* src = (pl ? g_ql : g_qh) + gbase + (size_t)(qt * AQ + row) * D_MODEL + c16 * 8;
        cpa16(dst, src);
    }
    const __half* kvsrc[2] = { g_kh, g_vh };
#pragma unroll
    for (int i = 0; i < 4; i++) {
        const int pl = i >> 1;
        int c = (i & 1) * 256 + tid;
        int row = c >> 3, c16 = c & 7;
        uint32_t dst = sBUF + pl * 8192 + (uint32_t)(row * 128 + ((c16 ^ (row & 7)) << 4));
        cpa16(dst, kvsrc[pl] + gbase + (size_t)row * D_MODEL + c16 * 8);
    }
    CP_COMMIT();
#pragma unroll
    for (int i = 0; i < 4; i++) {
        const int pl = i >> 1;
        int c = (i & 1) * 256 + tid;
        int row = c >> 3, c16 = c & 7;
        uint32_t dst = sBUF + 16384 + pl * 8192 + (uint32_t)(row * 128 + ((c16 ^ (row & 7)) << 4));
        cpa16(dst, kvsrc[pl] + gbase + (size_t)(AK + row) * D_MODEL + c16 * 8);
    }
    CP_COMMIT();

    uint32_t qfh[4][4], qfl[4][4];
    float O[8][4];
#pragma unroll
    for (int g = 0; g < 8; g++)
#pragma unroll
        for (int r = 0; r < 4; r++) O[g][r] = 0.f;
    float m0 = -1e30f, m1 = -1e30f, l0 = 0.f, l1 = 0.f;

    const int wrow0 = qt * AQ + wid * 16;
    const float scale = 0.125f;

    for (int jt = 0; jt < nkt; jt++) {
        if (jt + 1 < nkt) { CP_WAIT(1); } else { CP_WAIT(0); }
        __syncthreads();

        if (jt == 0) {
#pragma unroll
            for (int ks = 0; ks < 4; ks++) {
                int row = (wid << 4) + (lane & 15);
                int c16 = 2 * ks + (lane >> 4);
                uint32_t addr = (uint32_t)(row * 128 + ((c16 ^ (row & 7)) << 4));
                ldsm4(qfh[ks], sQh + addr);
                ldsm4(qfl[ks], sQl + addr);
            }
        }

        const uint32_t kb = sBUF + (uint32_t)(jt & 1) * 16384;
        const uint32_t sKh = kb, sVh = kb + 8192;

        if (wrow0 + 15 >= jt * AK) {
            float S[8][4];
#pragma unroll
            for (int g = 0; g < 8; g++)
#pragma unroll
                for (int r = 0; r < 4; r++) S[g][r] = 0.f;

#pragma unroll
            for (int ks = 0; ks < 4; ks++) {
                uint32_t kh[4][4];
#pragma unroll
                for (int g2 = 0; g2 < 4; g2++) {
                    int key = g2 * 16 + (lane & 7) + ((lane >> 4) & 1) * 8;
                    int c16 = 2 * ks + ((lane >> 3) & 1);
                    uint32_t addr = (uint32_t)(key * 128 + ((c16 ^ (key & 7)) << 4));
                    ldsm4(kh[g2], sKh + addr);
                }
#pragma unroll
                for (int g2 = 0; g2 < 4; g2++) {
                    mma_f16(S[2 * g2],     qfh[ks], &kh[g2][0]);
                    mma_f16(S[2 * g2],     qfl[ks], &kh[g2][0]);
                    mma_f16(S[2 * g2 + 1], qfh[ks], &kh[g2][2]);
                    mma_f16(S[2 * g2 + 1], qfl[ks], &kh[g2][2]);
                }
            }

            const int r0g = wrow0 + (lane >> 2);
            const bool domask = (jt * AK + 63) > wrow0;
            if (domask) {
                const int key0 = jt * AK + 2 * (lane & 3);
#pragma unroll
                for (int g = 0; g < 8; g++) {
                    int kk = key0 + 8 * g;
                    S[g][0] = (kk     <= r0g)     ? S[g][0] * scale : -1e30f;
                    S[g][1] = (kk + 1 <= r0g)     ? S[g][1] * scale : -1e30f;
                    S[g][2] = (kk     <= r0g + 8) ? S[g][2] * scale : -1e30f;
                    S[g][3] = (kk + 1 <= r0g + 8) ? S[g][3] * scale : -1e30f;
                }
            } else {
#pragma unroll
                for (int g = 0; g < 8; g++) {
                    S[g][0] *= scale; S[g][1] *= scale;
                    S[g][2] *= scale; S[g][3] *= scale;
                }
            }

            float mx0 = S[0][0], mx1 = S[0][2];
#pragma unroll
            for (int g = 0; g < 8; g++) {
                mx0 = fmaxf(mx0, fmaxf(S[g][0], S[g][1]));
                mx1 = fmaxf(mx1, fmaxf(S[g][2], S[g][3]));
            }
            mx0 = fmaxf(mx0, __shfl_xor_sync(0xffffffffu, mx0, 1));
            mx0 = fmaxf(mx0, __shfl_xor_sync(0xffffffffu, mx0, 2));
            mx1 = fmaxf(mx1, __shfl_xor_sync(0xffffffffu, mx1, 1));
            mx1 = fmaxf(mx1, __shfl_xor_sync(0xffffffffu, mx1, 2));
            float mn0 = fmaxf(m0, mx0), mn1 = fmaxf(m1, mx1);
            float corr0 = __expf(m0 - mn0), corr1 = __expf(m1 - mn1);
            m0 = mn0; m1 = mn1;

            float la0 = 0.f, la1 = 0.f;
            uint32_t ph[4][4], pl[4][4];
#pragma unroll
            for (int j = 0; j < 4; j++) {
                float p00 = __expf(S[2 * j][0] - mn0);
                float p01 = __expf(S[2 * j][1] - mn0);
                float p10 = __expf(S[2 * j][2] - mn1);
                float p11 = __expf(S[2 * j][3] - mn1);
                float p20 = __expf(S[2 * j + 1][0] - mn0);
                float p21 = __expf(S[2 * j + 1][1] - mn0);
                float p30 = __expf(S[2 * j + 1][2] - mn1);
                float p31 = __expf(S[2 * j + 1][3] - mn1);
                la0 += p00 + p01 + p20 + p21;
                la1 += p10 + p11 + p30 + p31;
                split2h(p00, p01, ph[j][0], pl[j][0]);
                split2h(p10, p11, ph[j][1], pl[j][1]);
                split2h(p20, p21, ph[j][2], pl[j][2]);
                split2h(p30, p31, ph[j][3], pl[j][3]);
            }
            l0 = l0 * corr0 + la0;
            l1 = l1 * corr1 + la1;
#pragma unroll
            for (int g = 0; g < 8; g++) {
                O[g][0] *= corr0; O[g][1] *= corr0;
                O[g][2] *= corr1; O[g][3] *= corr1;
            }

#pragma unroll
            for (int ks = 0; ks < 4; ks++) {
                uint32_t vh[4][4];
#pragma unroll
                for (int d2 = 0; d2 < 4; d2++) {
                    int row = 16 * ks + (lane & 7) + ((lane >> 3) & 1) * 8;
                    int c16 = 2 * d2 + ((lane >> 4) & 1);
                    uint32_t addr = (uint32_t)(row * 128 + ((c16 ^ (row & 7)) << 4));
                    ldsm4t(vh[d2], sVh + addr);
                }
#pragma unroll
                for (int d2 = 0; d2 < 4; d2++) {
                    mma_f16(O[2 * d2],     ph[ks], &vh[d2][0]);
                    mma_f16(O[2 * d2],     pl[ks], &vh[d2][0]);
                    mma_f16(O[2 * d2 + 1], ph[ks], &vh[d2][2]);
                    mma_f16(O[2 * d2 + 1], pl[ks], &vh[d2][2]);
                }
            }
        }

        __syncthreads();
        if (jt + 2 < nkt) {
#pragma unroll
            for (int i = 0; i < 4; i++) {
                const int pl2 = i >> 1;
                int c = (i & 1) * 256 + tid;
                int row = c >> 3, c16 = c & 7;
                uint32_t dst = sBUF + (uint32_t)(jt & 1) * 16384 + pl2 * 8192
                             + (uint32_t)(row * 128 + ((c16 ^ (row & 7)) << 4));
                cpa16(dst, kvsrc[pl2] + gbase + (size_t)((jt + 2) * AK + row) * D_MODEL + c16 * 8);
            }
            CP_COMMIT();
        }
    }

    // ---- epilogue: normalize, split, write ctx planes ----
    l0 += __shfl_xor_sync(0xffffffffu, l0, 1);
    l0 += __shfl_xor_sync(0xffffffffu, l0, 2);
    l1 += __shfl_xor_sync(0xffffffffu, l1, 1);
    l1 += __shfl_xor_sync(0xffffffffu, l1, 2);
    float inv0 = 1.f / l0, inv1 = 1.f / l1;
    const int r0g = wrow0 + (lane >> 2);
#pragma unroll
    for (int g = 0; g < 8; g++) {
        int dim = 8 * g + 2 * (lane & 3);
        uint32_t hh, ll;
        split2h(O[g][0] * inv0, O[g][1] * inv0, hh, ll);
        *(uint32_t*)(g_ctxh + gbase + (size_t)r0g * D_MODEL + dim) = hh;
        *(uint32_t*)(g_ctxl + gbase + (size_t)r0g * D_MODEL + dim) = ll;
        split2h(O[g][2] * inv1, O[g][3] * inv1, hh, ll);
        *(uint32_t*)(g_ctxh + gbase + (size_t)(r0g + 8) * D_MODEL + dim) = hh;
        *(uint32_t*)(g_ctxl + gbase + (size_t)(r0g + 8) * D_MODEL + dim) = ll;
    }
}

// ===========================================================================
extern "C" void kernel_launch(void* const* d_in, const int* in_sizes, int n_in,
                              void* d_out, int out_size)
{
    const float* query = (const float*)d_in[0];
    const float* key   = (const float*)d_in[1];
    const float* value = (const float*)d_in[2];
    // d_in[3] = mask — causal, applied analytically in-kernel
    const float* w_q = (const float*)d_in[4];
    const float* b_q = (const float*)d_in[5];
    const float* w_k = (const float*)d_in[6];
    const float* b_k = (const float*)d_in[7];
    const float* w_v = (const float*)d_in[8];
    const float* b_v = (const float*)d_in[9];
    const float* w_o = (const float*)d_in[10];
    const float* b_o = (const float*)d_in[11];
    float* out = (float*)d_out;

    const int M  = in_sizes[0] / D_MODEL;   // B * S
    const int Bn = M / SEQ;

    cudaFuncSetAttribute(attn_mma_kernel,
                         cudaFuncAttributeMaxDynamicSharedMemorySize, ATTN_SMEM);

    split_w_kernel<<<dim3(256, 1, 4), 256>>>(w_q, w_k, w_v, w_o);

    gemm_qkv_kernel<<<dim3(D_MODEL / 128, M / 128, 3), 256>>>(
        query, key, value, b_q, b_k, b_v);

    attn_mma_kernel<<<dim3(SEQ / AQ, NHEAD, Bn), 256, ATTN_SMEM>>>();

    gemm_out_kernel<<<dim3(D_MODEL / 128, M / 128), 256>>>(b_o, out);
}